// round 1
// baseline (speedup 1.0000x reference)
#include <cuda_runtime.h>
#include <math.h>

#define H 256
#define W 832
#define B 2
#define HW (H*W)
#define INFV 1e9f
#define CAP 65536

// Scratch (static __device__ — no allocations allowed)
__device__ float g_blur[2*B*HW];    // [2B][HW]: maps 0..B-1 = src batches, B..2B-1 = dst batches
__device__ float g_theta[2*B*HW];
__device__ float g_nx[B*HW];
__device__ float g_ny[B*HW];
__device__ float g_den[B*HW];
__device__ float g_wk[1024];
__device__ int   g_count;
__device__ int   g_pt_pos[CAP];     // flat index b*HW + i*W + j
__device__ float g_pt_dx[CAP];
__device__ float g_pt_dy[CAP];

// --- 1. circular 3x3 box blur of src & dst (matches jnp.roll wraparound) ---
__global__ void blur_kernel(const float* __restrict__ src, const float* __restrict__ dst) {
    int idx = blockIdx.x * blockDim.x + threadIdx.x;
    if (idx >= 2*B*HW) return;
    int m = idx / HW;
    int p = idx % HW;
    int i = p / W, j = p % W;
    const float* map = (m < B) ? (src + m*HW) : (dst + (m - B)*HW);
    float s = 0.f;
    #pragma unroll
    for (int di = -1; di <= 1; di++) {
        int ii = i + di; ii = (ii < 0) ? ii + H : (ii >= H ? ii - H : ii);
        #pragma unroll
        for (int dj = -1; dj <= 1; dj++) {
            int jj = j + dj; jj = (jj < 0) ? jj + W : (jj >= W ? jj - W : jj);
            s += map[ii*W + jj];
        }
    }
    g_blur[idx] = s;
}

// --- 2. orientation = atan2(gy, gx), jnp.gradient border rules ---
__global__ void theta_kernel() {
    int idx = blockIdx.x * blockDim.x + threadIdx.x;
    if (idx >= 2*B*HW) return;
    int m = idx / HW;
    int p = idx % HW;
    int i = p / W, j = p % W;
    const float* b = g_blur + m*HW;
    float gy, gx;
    if (i == 0)        gy = b[W + j] - b[j];
    else if (i == H-1) gy = b[(H-1)*W + j] - b[(H-2)*W + j];
    else               gy = 0.5f * (b[(i+1)*W + j] - b[(i-1)*W + j]);
    if (j == 0)        gx = b[i*W + 1] - b[i*W];
    else if (j == W-1) gx = b[i*W + W-1] - b[i*W + W-2];
    else               gx = 0.5f * (b[i*W + j+1] - b[i*W + j-1]);
    g_theta[idx] = atan2f(gy, gx);
}

// --- 3. zero accumulators, build weight table, reset point counter ---
__global__ void init_kernel(const int* __restrict__ cxx, const int* __restrict__ cyy, int C) {
    int idx = blockIdx.x * blockDim.x + threadIdx.x;
    if (idx < B*HW) {
        g_nx[idx] = 0.f; g_ny[idx] = 0.f; g_den[idx] = 0.f;
    }
    if (idx < C) {
        float d = sqrtf((float)(cxx[idx]*cxx[idx] + cyy[idx]*cyy[idx]));
        g_wk[idx] = expf(-d / 5.0f);   // 0.5 * SENSE_RANGE = 5
    }
    if (idx == 0) g_count = 0;
}

// --- 4. sparsify edges + windowed correspondence search, append active points ---
__global__ void points_kernel(const float* __restrict__ src, const float* __restrict__ dst,
                              const int* __restrict__ xx, const int* __restrict__ yy, int K,
                              const int* __restrict__ sxx, const int* __restrict__ syy, int S) {
    int idx = blockIdx.x * blockDim.x + threadIdx.x;
    if (idx >= B*HW) return;
    int b = idx / HW;
    int p = idx % HW;
    int i = p / W, j = p % W;
    const float* s = src + b*HW;
    if (s[p] <= 0.5f) return;                    // not an edge pixel (~98% exit)

    // keep iff no edge pixel with smaller linear index in the sparsity window
    int ownlin = p;
    for (int k = 0; k < S; k++) {
        int ii = i + syy[k], jj = j + sxx[k];
        if (ii < 0 || ii >= H || jj < 0 || jj >= W) continue;
        int q = ii*W + jj;
        if (q < ownlin && s[q] > 0.5f) return;   // a smaller-index edge wins
    }

    const float* d      = dst + b*HW;
    const float* td_map = g_theta + (B + b)*HW;
    float ts = g_theta[b*HW + p];

    float best = INFV, bdx = 0.f, bdy = 0.f;
    for (int k = 0; k < K; k++) {                // offsets pre-sorted; first-min = argmin
        int ox = xx[k], oy = yy[k];
        int ii = i + oy, jj = j + ox;
        if (ii < 0 || ii >= H || jj < 0 || jj >= W) continue;
        int q = ii*W + jj;
        if (d[q] > 0.5f) {
            float dist = sqrtf((float)(ox*ox + oy*oy));
            float ang  = 1.0f - cosf(ts - td_map[q]);
            float sc   = 20.0f * dist + 10.5f * ang;   // PIX_W, MULLINE_W*ALPHA_W
            if (sc < best) { best = sc; bdx = (float)ox; bdy = (float)oy; }
        }
    }
    if (best < 0.5f * INFV) {
        int slot = atomicAdd(&g_count, 1);
        if (slot < CAP) {
            g_pt_pos[slot] = idx;
            g_pt_dx[slot]  = bdx;
            g_pt_dy[slot]  = bdy;
        }
    }
}

// --- 5. scatter-diffuse sparse displacements (inverse of the dense 441-tap gather) ---
__global__ void scatter_kernel(const int* __restrict__ cxx, const int* __restrict__ cyy, int C) {
    int n = g_count; if (n > CAP) n = CAP;
    int total = n * C;
    int stride = gridDim.x * blockDim.x;
    for (int t = blockIdx.x * blockDim.x + threadIdx.x; t < total; t += stride) {
        int pt = t / C, k = t - pt * C;
        int pos = g_pt_pos[pt];
        int b = pos / HW;
        int p = pos % HW;
        int i = p / W, j = p % W;
        // offsets are symmetric: scattering q -> q+off with w(|off|) equals the gather
        int ii = i + cyy[k], jj = j + cxx[k];
        if (ii < 0 || ii >= H || jj < 0 || jj >= W) continue;
        float w = g_wk[k];
        int q = b*HW + ii*W + jj;
        atomicAdd(&g_nx[q],  w * g_pt_dx[pt]);
        atomicAdd(&g_ny[q],  w * g_pt_dy[pt]);
        atomicAdd(&g_den[q], w);
    }
}

// --- 6. finalize: coord + ALPHA_PAD * n / (den + 1e-6) ---
__global__ void final_kernel(float* __restrict__ out) {
    int idx = blockIdx.x * blockDim.x + threadIdx.x;
    if (idx >= B*HW) return;
    int b = idx / HW;
    int p = idx % HW;
    int i = p / W, j = p % W;
    float inv = 1.0f / (g_den[idx] + 1e-6f);
    float mdx = 0.6f * g_nx[idx] * inv;
    float mdy = 0.6f * g_ny[idx] * inv;
    out[b*2*HW + p]      = (float)j + mdx;   // morphedx
    out[b*2*HW + HW + p] = (float)i + mdy;   // morphedy
}

extern "C" void kernel_launch(void* const* d_in, const int* in_sizes, int n_in,
                              void* d_out, int out_size) {
    const float* src = (const float*)d_in[0];
    const float* dst = (const float*)d_in[1];
    const int* xx  = (const int*)d_in[2];
    const int* yy  = (const int*)d_in[3];
    const int* sxx = (const int*)d_in[4];
    const int* syy = (const int*)d_in[5];
    const int* cxx = (const int*)d_in[6];
    const int* cyy = (const int*)d_in[7];
    int K = in_sizes[2];   // 105 search offsets
    int S = in_sizes[4];   // 25 sparsity offsets
    int C = in_sizes[6];   // 441 sense offsets
    float* out = (float*)d_out;

    int n2 = 2*B*HW;
    blur_kernel   <<<(n2 + 255)/256, 256>>>(src, dst);
    theta_kernel  <<<(n2 + 255)/256, 256>>>();
    init_kernel   <<<(B*HW + 255)/256, 256>>>(cxx, cyy, C);
    points_kernel <<<(B*HW + 255)/256, 256>>>(src, dst, xx, yy, K, sxx, syy, S);
    scatter_kernel<<<1024, 256>>>(cxx, cyy, C);
    final_kernel  <<<(B*HW + 255)/256, 256>>>(out);
}

// round 2
// speedup vs baseline: 1.5615x; 1.5615x over previous
#include <cuda_runtime.h>
#include <math.h>

#define H 256
#define W 832
#define B 2
#define HW (H*W)
#define INFV 1e9f
#define CAP 32768

// Scratch (static __device__ — allocations forbidden)
__device__ float g_acc[3*B*HW];   // [0]=nx, [1]=ny, [2]=den planes
__device__ int   g_cnt[2];        // [0]=kept count, [1]=active count
__device__ int   g_kept[CAP];     // flat index b*HW + p of kept (sparsified) edge pixels
__device__ int   g_pt_pos[CAP];   // active points (survived search)
__device__ float g_pt_dx[CAP];
__device__ float g_pt_dy[CAP];

// circular 3x3 box blur value at (i,j)  (matches sum of jnp.roll wraps)
__device__ __forceinline__ float blur_at(const float* __restrict__ m, int i, int j) {
    float s = 0.f;
    #pragma unroll
    for (int di = -1; di <= 1; di++) {
        int ii = i + di; ii = (ii < 0) ? ii + H : (ii >= H ? ii - H : ii);
        #pragma unroll
        for (int dj = -1; dj <= 1; dj++) {
            int jj = j + dj; jj = (jj < 0) ? jj + W : (jj >= W ? jj - W : jj);
            s += m[ii*W + jj];
        }
    }
    return s;
}

// orientation = atan2(gy,gx) of blurred map, jnp.gradient border rules
__device__ __forceinline__ float theta_at(const float* __restrict__ m, int i, int j) {
    float gy, gx;
    if (i == 0)        gy = blur_at(m, 1, j)   - blur_at(m, 0, j);
    else if (i == H-1) gy = blur_at(m, H-1, j) - blur_at(m, H-2, j);
    else               gy = 0.5f * (blur_at(m, i+1, j) - blur_at(m, i-1, j));
    if (j == 0)        gx = blur_at(m, i, 1)   - blur_at(m, i, 0);
    else if (j == W-1) gx = blur_at(m, i, W-1) - blur_at(m, i, W-2);
    else               gx = 0.5f * (blur_at(m, i, j+1) - blur_at(m, i, j-1));
    return atan2f(gy, gx);
}

// --- A: edge test + sparsify, compact kept pixels ---
__global__ void compact_kernel(const float* __restrict__ src,
                               const int* __restrict__ sxx, const int* __restrict__ syy, int S) {
    int idx = blockIdx.x * blockDim.x + threadIdx.x;
    if (idx >= B*HW) return;
    int b = idx / HW;
    int p = idx % HW;
    const float* s = src + b*HW;
    if (s[p] <= 0.5f) return;                        // ~98% of threads exit here
    int i = p / W, j = p % W;
    for (int k = 0; k < S; k++) {
        int ii = i + syy[k], jj = j + sxx[k];
        if (ii < 0 || ii >= H || jj < 0 || jj >= W) continue;
        int q = ii*W + jj;
        if (q < p && s[q] > 0.5f) return;            // smaller-linear-index edge wins
    }
    int slot = atomicAdd(&g_cnt[0], 1);
    if (slot < CAP) g_kept[slot] = idx;
}

// --- B: warp-per-kept-point correspondence search (lanes split the K offsets) ---
__global__ void search_kernel(const float* __restrict__ src, const float* __restrict__ dst,
                              const int* __restrict__ xx, const int* __restrict__ yy, int K) {
    int gw    = (blockIdx.x * blockDim.x + threadIdx.x) >> 5;
    int lane  = threadIdx.x & 31;
    int nWarp = (gridDim.x * blockDim.x) >> 5;
    int n = g_cnt[0]; if (n > CAP) n = CAP;

    for (int pt = gw; pt < n; pt += nWarp) {
        int pos = g_kept[pt];
        int b = pos / HW, p = pos % HW;
        int i = p / W,   j = p % W;
        const float* s = src + b*HW;
        const float* d = dst + b*HW;

        float ts = 0.f;
        if (lane == 0) ts = theta_at(s, i, j);
        ts = __shfl_sync(0xffffffffu, ts, 0);

        float best = INFV; int bestk = K;
        for (int k = lane; k < K; k += 32) {         // per-lane k strictly increasing
            int ox = xx[k], oy = yy[k];
            int ii = i + oy, jj = j + ox;
            if (ii < 0 || ii >= H || jj < 0 || jj >= W) continue;
            if (d[ii*W + jj] > 0.5f) {               // rare (~2% density)
                float td = theta_at(d, ii, jj);
                float sc = 20.0f * sqrtf((float)(ox*ox + oy*oy))
                         + 10.5f * (1.0f - cosf(ts - td));
                if (sc < best) { best = sc; bestk = k; }
            }
        }
        // warp argmin with first-index tie-break (reference = argmin over sorted order)
        #pragma unroll
        for (int off = 16; off; off >>= 1) {
            float s2 = __shfl_xor_sync(0xffffffffu, best,  off);
            int   k2 = __shfl_xor_sync(0xffffffffu, bestk, off);
            if (s2 < best || (s2 == best && k2 < bestk)) { best = s2; bestk = k2; }
        }
        if (lane == 0 && best < 0.5f * INFV) {
            int slot = atomicAdd(&g_cnt[1], 1);
            if (slot < CAP) {
                g_pt_pos[slot] = pos;
                g_pt_dx[slot]  = (float)xx[bestk];
                g_pt_dy[slot]  = (float)yy[bestk];
            }
        }
    }
}

// --- C: scatter-diffuse sparse displacements over the 21x21 sense window ---
__global__ void scatter_kernel(const int* __restrict__ cxx, const int* __restrict__ cyy, int C) {
    int n = g_cnt[1]; if (n > CAP) n = CAP;
    int total = n * C;
    int stride = gridDim.x * blockDim.x;
    float* nx  = g_acc;
    float* ny  = g_acc + B*HW;
    float* den = g_acc + 2*B*HW;
    for (int t = blockIdx.x * blockDim.x + threadIdx.x; t < total; t += stride) {
        int pt = t / C, k = t - pt * C;
        int pos = g_pt_pos[pt];
        int b = pos / HW, p = pos % HW;
        int i = p / W,   j = p % W;
        int ox = cxx[k], oy = cyy[k];
        int ii = i + oy, jj = j + ox;                // offset set symmetric -> scatter == gather
        if (ii < 0 || ii >= H || jj < 0 || jj >= W) continue;
        float w = expf(-sqrtf((float)(ox*ox + oy*oy)) / 5.0f);
        int q = b*HW + ii*W + jj;
        atomicAdd(&nx[q],  w * g_pt_dx[pt]);
        atomicAdd(&ny[q],  w * g_pt_dy[pt]);
        atomicAdd(&den[q], w);
    }
}

// --- D: finalize coords ---
__global__ void final_kernel(float* __restrict__ out) {
    int idx = blockIdx.x * blockDim.x + threadIdx.x;
    if (idx >= B*HW) return;
    int b = idx / HW;
    int p = idx % HW;
    int i = p / W, j = p % W;
    float inv = 1.0f / (g_acc[2*B*HW + idx] + 1e-6f);
    float mdx = 0.6f * g_acc[idx]        * inv;
    float mdy = 0.6f * g_acc[B*HW + idx] * inv;
    out[b*2*HW + p]      = (float)j + mdx;   // morphedx
    out[b*2*HW + HW + p] = (float)i + mdy;   // morphedy
}

extern "C" void kernel_launch(void* const* d_in, const int* in_sizes, int n_in,
                              void* d_out, int out_size) {
    const float* src = (const float*)d_in[0];
    const float* dst = (const float*)d_in[1];
    const int* xx  = (const int*)d_in[2];
    const int* yy  = (const int*)d_in[3];
    const int* sxx = (const int*)d_in[4];
    const int* syy = (const int*)d_in[5];
    const int* cxx = (const int*)d_in[6];
    const int* cyy = (const int*)d_in[7];
    int K = in_sizes[2];   // 105 search offsets
    int S = in_sizes[4];   // 25 sparsity offsets
    int C = in_sizes[6];   // 441 sense offsets
    float* out = (float*)d_out;

    void *acc_p = nullptr, *cnt_p = nullptr;
    cudaGetSymbolAddress(&acc_p, g_acc);
    cudaGetSymbolAddress(&cnt_p, g_cnt);
    cudaMemsetAsync(acc_p, 0, 3*B*HW*sizeof(float));
    cudaMemsetAsync(cnt_p, 0, 2*sizeof(int));

    compact_kernel<<<(B*HW + 255)/256, 256>>>(src, sxx, syy, S);
    search_kernel <<<296, 256>>>(src, dst, xx, yy, K);
    scatter_kernel<<<2048, 256>>>(cxx, cyy, C);
    final_kernel  <<<(B*HW + 255)/256, 256>>>(out);
}